// round 11
// baseline (speedup 1.0000x reference)
#include <cuda_runtime.h>
#include <cuda_bf16.h>

#define NN 20000
#define DD 32
#define HH 64
#define GG 256
#define NT 64      // nodes per LSTM CTA (4 warp-pairs x 16)
#define HSTR2 68   // node-dim stride (4*17: conflict-free for strided STS/LDS)

typedef unsigned long long u64;
typedef unsigned int u32;

// ---------------- device scratch ----------------
__device__ int   g_nbrs[NN * DD];
__device__ float g_bufA[NN * HH];
__device__ float g_bufB[NN * HH];
__device__ float g_proj[NN * GG];
__device__ float g_agg [NN * HH];
__device__ float g_wT  [HH * GG];    // W_hh transposed: [k][g]

__device__ __forceinline__ float tanhx(float x) {
    float y; asm("tanh.approx.f32 %0, %1;" : "=f"(y) : "f"(x)); return y;
}
__device__ __forceinline__ float sigmx(float x) {
    return fmaf(tanhx(0.5f * x), 0.5f, 0.5f);
}
__device__ __forceinline__ u64 pack2(float lo, float hi) {
    u64 r;
    asm("mov.b64 %0, {%1, %2};" : "=l"(r) : "r"(__float_as_uint(lo)), "r"(__float_as_uint(hi)));
    return r;
}
__device__ __forceinline__ void unpack2(u64 v, float& lo, float& hi) {
    u32 a, b;
    asm("mov.b64 {%0, %1}, %2;" : "=r"(a), "=r"(b) : "l"(v));
    lo = __uint_as_float(a); hi = __uint_as_float(b);
}
__device__ __forceinline__ u64 fma2(u64 a, u64 b, u64 c) {
    u64 d;
    asm("fma.rn.f32x2 %0, %1, %2, %3;" : "=l"(d) : "l"(a), "l"(b), "l"(c));
    return d;
}

// ---------------- sort neighbor rows ----------------
__global__ void sort_kernel(const int* __restrict__ nbr) {
    int node = blockIdx.x * blockDim.x + threadIdx.x;
    if (node >= NN) return;
    int v[DD];
#pragma unroll
    for (int i = 0; i < DD; i++) v[i] = nbr[node * DD + i];
#pragma unroll
    for (int k = 2; k <= DD; k <<= 1)
#pragma unroll
        for (int j = k >> 1; j > 0; j >>= 1)
#pragma unroll
            for (int i = 0; i < DD; i++) {
                int l = i ^ j;
                if (l > i) {
                    int a = v[i], b = v[l];
                    if ((a > b) == ((i & k) == 0)) { v[i] = b; v[l] = a; }
                }
            }
#pragma unroll
    for (int i = 0; i < DD; i++) g_nbrs[node * DD + i] = v[i];
}

// ---------------- transpose W_hh -> g_wT[k][g] ----------------
__global__ void transw_kernel(const float* __restrict__ W) {
    int k = blockIdx.x, g = threadIdx.x;
    g_wT[k * GG + g] = W[g * HH + k];
}

// ---------------- proj = x @ W_ih^T + b_ih + b_hh  (32 nodes/block) -------
__global__ void proj_kernel(const float* __restrict__ x, int in_d,
                            const float* __restrict__ W_ih,
                            const float* __restrict__ b_ih,
                            const float* __restrict__ b_hh) {
    extern __shared__ float smf[];
    float* sW = smf;
    float* sB = sW + in_d * GG;
    float* sX = sB + GG;
    int tid = threadIdx.x;
    for (int idx = tid; idx < in_d * GG; idx += 256) {
        int g = idx / in_d, k = idx - g * in_d;
        sW[k * GG + g] = W_ih[idx];
    }
    if (tid < GG) sB[tid] = b_ih[tid] + b_hh[tid];
    int node0 = blockIdx.x * 32;
    for (int idx = tid; idx < 32 * in_d; idx += 256) {
        int i = idx / in_d, k = idx - i * in_d;
        sX[idx] = x[(node0 + i) * in_d + k];
    }
    __syncthreads();
    int w = tid >> 5, tg = tid & 31;
    float acc[4][8];
#pragma unroll
    for (int i = 0; i < 4; i++)
#pragma unroll
        for (int j = 0; j < 8; j++) acc[i][j] = sB[tg + 32 * j];
    for (int k = 0; k < in_d; k++) {
        float xv[4];
#pragma unroll
        for (int i = 0; i < 4; i++) xv[i] = sX[(w * 4 + i) * in_d + k];
#pragma unroll
        for (int j = 0; j < 8; j++) {
            float b = sW[k * GG + tg + 32 * j];
#pragma unroll
            for (int i = 0; i < 4; i++) acc[i][j] += xv[i] * b;
        }
    }
#pragma unroll
    for (int i = 0; i < 4; i++) {
        int node = node0 + w * 4 + i;
#pragma unroll
        for (int j = 0; j < 8; j++) g_proj[node * GG + tg + 32 * j] = acc[i][j];
    }
}

// ---------------- LSTM recurrence: warp-pair / 16-node design -------------
// CTA: 256 threads = 8 warps = 4 pairs x 16 nodes = 64 nodes.
// Warp role r handles hidden half [32r,32r+32): lane tg owns hidden 32r+tg
// for all 16 nodes. Per-pair named barrier per step; no CTA-wide sync.
__global__ __launch_bounds__(256, 2)
void lstm_kernel() {
    __shared__ float sH[2][HH][HSTR2];   // 34.8 KB
    int tid = threadIdx.x, tg = tid & 31, w = tid >> 5;
    int r = w & 1, pair = w >> 1;
    int nbase = pair * 16;
    int node0 = blockIdx.x * NT + nbase;
    int gl = r * 32 + tg;                // hidden unit / gate lane in 64-block
    const float* wP = g_wT + gl;

    float c[16];
#pragma unroll
    for (int i = 0; i < 16; i++) c[i] = 0.f;

#pragma unroll 1
    for (int t = 0; t < DD; t++) {
        u64 acc[4][8];   // [gate stream j][node pair m]
        // gather: proj of t-th sorted neighbor; streams j at gate j*64+gl
#pragma unroll
        for (int m = 0; m < 8; m++) {
            int na = node0 + 2 * m, nb = na + 1;
            int ia = (na < NN) ? g_nbrs[na * DD + t] : 0;
            int ib = (nb < NN) ? g_nbrs[nb * DD + t] : 0;
            const float* pa = g_proj + (size_t)ia * GG + gl;
            const float* pb = g_proj + (size_t)ib * GG + gl;
#pragma unroll
            for (int j = 0; j < 4; j++)
                acc[j][m] = pack2(__ldg(&pa[j * 64]), __ldg(&pb[j * 64]));
        }
        if (t) {
            const float* sHr = &sH[t & 1][0][nbase];
#pragma unroll 2
            for (int k = 0; k < HH; k++) {
                const float* wk = wP + k * GG;
                float w0 = __ldg(wk);
                float w1 = __ldg(wk + 64);
                float w2 = __ldg(wk + 128);
                float w3 = __ldg(wk + 192);
                u64 b0 = pack2(w0, w0), b1 = pack2(w1, w1);
                u64 b2 = pack2(w2, w2), b3 = pack2(w3, w3);
                const float4* ar = (const float4*)(sHr + k * HSTR2);
                float4 q0 = ar[0], q1 = ar[1], q2 = ar[2], q3 = ar[3];  // 16 h vals, broadcast
                u64 a0 = *(const u64*)&q0.x, a1 = *(const u64*)&q0.z;
                u64 a2 = *(const u64*)&q1.x, a3 = *(const u64*)&q1.z;
                u64 a4 = *(const u64*)&q2.x, a5 = *(const u64*)&q2.z;
                u64 a6 = *(const u64*)&q3.x, a7 = *(const u64*)&q3.z;
                acc[0][0] = fma2(a0, b0, acc[0][0]); acc[1][0] = fma2(a0, b1, acc[1][0]);
                acc[2][0] = fma2(a0, b2, acc[2][0]); acc[3][0] = fma2(a0, b3, acc[3][0]);
                acc[0][1] = fma2(a1, b0, acc[0][1]); acc[1][1] = fma2(a1, b1, acc[1][1]);
                acc[2][1] = fma2(a1, b2, acc[2][1]); acc[3][1] = fma2(a1, b3, acc[3][1]);
                acc[0][2] = fma2(a2, b0, acc[0][2]); acc[1][2] = fma2(a2, b1, acc[1][2]);
                acc[2][2] = fma2(a2, b2, acc[2][2]); acc[3][2] = fma2(a2, b3, acc[3][2]);
                acc[0][3] = fma2(a3, b0, acc[0][3]); acc[1][3] = fma2(a3, b1, acc[1][3]);
                acc[2][3] = fma2(a3, b2, acc[2][3]); acc[3][3] = fma2(a3, b3, acc[3][3]);
                acc[0][4] = fma2(a4, b0, acc[0][4]); acc[1][4] = fma2(a4, b1, acc[1][4]);
                acc[2][4] = fma2(a4, b2, acc[2][4]); acc[3][4] = fma2(a4, b3, acc[3][4]);
                acc[0][5] = fma2(a5, b0, acc[0][5]); acc[1][5] = fma2(a5, b1, acc[1][5]);
                acc[2][5] = fma2(a5, b2, acc[2][5]); acc[3][5] = fma2(a5, b3, acc[3][5]);
                acc[0][6] = fma2(a6, b0, acc[0][6]); acc[1][6] = fma2(a6, b1, acc[1][6]);
                acc[2][6] = fma2(a6, b2, acc[2][6]); acc[3][6] = fma2(a6, b3, acc[3][6]);
                acc[0][7] = fma2(a7, b0, acc[0][7]); acc[1][7] = fma2(a7, b1, acc[1][7]);
                acc[2][7] = fma2(a7, b2, acc[2][7]); acc[3][7] = fma2(a7, b3, acc[3][7]);
            }
        }
        // cell update: lane owns hidden gl for nodes 2m,2m+1
        bool last = (t == DD - 1);
        float* sHw = &sH[(t + 1) & 1][gl][nbase];
#pragma unroll
        for (int m = 0; m < 8; m++) {
            float ia, ib, fa, fb, ga, gb, oa, ob;
            unpack2(acc[0][m], ia, ib);
            unpack2(acc[1][m], fa, fb);
            unpack2(acc[2][m], ga, gb);
            unpack2(acc[3][m], oa, ob);
            int n0 = 2 * m, n1 = 2 * m + 1;
            c[n0] = sigmx(fa) * c[n0] + sigmx(ia) * tanhx(ga);
            float ha = sigmx(oa) * tanhx(c[n0]);
            c[n1] = sigmx(fb) * c[n1] + sigmx(ib) * tanhx(gb);
            float hb = sigmx(ob) * tanhx(c[n1]);
            if (!last) {
                *(float2*)(sHw + 2 * m) = make_float2(ha, hb);
            } else {
                int na = node0 + n0, nb = na + 1;
                if (na < NN) g_agg[na * HH + gl] = ha;
                if (nb < NN) g_agg[nb * HH + gl] = hb;
            }
        }
        if (!last)
            asm volatile("bar.sync %0, %1;" :: "r"(pair + 1), "r"(64) : "memory");
    }
}

// ---------------- h_next = relu([x, agg] @ Wl^T + bl)  (32 nodes/block) ---
__global__ void combine_kernel(const float* __restrict__ x, int in_d,
                               const float* __restrict__ Wl,
                               const float* __restrict__ bl,
                               float* __restrict__ out) {
    extern __shared__ float smf[];
    int C = in_d + HH;
    float* sW = smf;
    float* sB = sW + C * HH;
    float* sX = sB + HH;
    int tid = threadIdx.x;
    for (int idx = tid; idx < C * HH; idx += 256) {
        int o = idx / C, k = idx - o * C;
        sW[k * HH + o] = Wl[idx];
    }
    if (tid < HH) sB[tid] = bl[tid];
    int node0 = blockIdx.x * 32;
    for (int idx = tid; idx < 32 * C; idx += 256) {
        int i = idx / C, k = idx - i * C;
        sX[idx] = (k < in_d) ? x[(node0 + i) * in_d + k]
                             : g_agg[(node0 + i) * HH + (k - in_d)];
    }
    __syncthreads();
    int w = tid >> 5, tg = tid & 31;
    u64 acc[4];
#pragma unroll
    for (int i = 0; i < 4; i++) acc[i] = *(const u64*)(sB + 2 * tg);
    for (int k = 0; k < C; k++) {
        u64 wp = *(const u64*)(sW + k * HH + 2 * tg);
#pragma unroll
        for (int i = 0; i < 4; i++) {
            float xv = sX[(w * 4 + i) * C + k];
            acc[i] = fma2(pack2(xv, xv), wp, acc[i]);
        }
    }
#pragma unroll
    for (int i = 0; i < 4; i++) {
        float a0, a1;
        unpack2(acc[i], a0, a1);
        int node = node0 + w * 4 + i;
        *(float2*)(out + node * HH + 2 * tg) = make_float2(fmaxf(a0, 0.f), fmaxf(a1, 0.f));
    }
}

// ---------------- out = h @ W_out^T + b_out ----------------
__global__ void out_kernel(const float* __restrict__ h,
                           const float* __restrict__ W_out,
                           const float* __restrict__ b_out,
                           float* __restrict__ out) {
    int tid = threadIdx.x;
    int node = blockIdx.x * 8 + (tid >> 5);
    int tg = tid & 31;
    float a = h[node * HH + tg] * W_out[tg] + h[node * HH + tg + 32] * W_out[tg + 32];
#pragma unroll
    for (int s = 16; s > 0; s >>= 1) a += __shfl_down_sync(0xffffffffu, a, s);
    if (tg == 0) out[node] = a + b_out[0];
}

// ---------------- launcher ----------------
extern "C" void kernel_launch(void* const* d_in, const int* in_sizes, int n_in,
                              void* d_out, int out_size) {
    const float* node_features = (const float*)d_in[0];
    const int*   nbr           = (const int*)d_in[1];
    const float *W_ih[3], *W_hh[3], *b_ih[3], *b_hh[3], *Wl[3], *bl[3];
    for (int l = 0; l < 3; l++) {
        W_ih[l] = (const float*)d_in[2 + 6 * l + 0];
        W_hh[l] = (const float*)d_in[2 + 6 * l + 1];
        b_ih[l] = (const float*)d_in[2 + 6 * l + 2];
        b_hh[l] = (const float*)d_in[2 + 6 * l + 3];
        Wl[l]   = (const float*)d_in[2 + 6 * l + 4];
        bl[l]   = (const float*)d_in[2 + 6 * l + 5];
    }
    const float* W_out = (const float*)d_in[20];
    const float* b_out = (const float*)d_in[21];
    float* out = (float*)d_out;

    float *bufA, *bufB;
    cudaGetSymbolAddress((void**)&bufA, g_bufA);
    cudaGetSymbolAddress((void**)&bufB, g_bufB);

    cudaFuncSetAttribute(proj_kernel, cudaFuncAttributeMaxDynamicSharedMemorySize, 80000);
    cudaFuncSetAttribute(combine_kernel, cudaFuncAttributeMaxDynamicSharedMemorySize, 56000);

    sort_kernel<<<(NN + 255) / 256, 256>>>(nbr);

    const float* x = node_features;
    float* nxt = bufA;
    int grid_lstm = (NN + NT - 1) / NT;   // 313
    for (int l = 0; l < 3; l++) {
        int in_d = (l == 0) ? 3 : 64;
        size_t proj_sm = (size_t)(in_d * GG + GG + 32 * in_d) * 4;
        transw_kernel<<<HH, GG>>>(W_hh[l]);
        proj_kernel<<<NN / 32, 256, proj_sm>>>(x, in_d, W_ih[l], b_ih[l], b_hh[l]);
        lstm_kernel<<<grid_lstm, 256>>>();
        int C = in_d + HH;
        size_t comb_sm = (size_t)(C * HH + HH + 32 * C) * 4;
        combine_kernel<<<NN / 32, 256, comb_sm>>>(x, in_d, Wl[l], bl[l], nxt);
        x = nxt;
        nxt = (nxt == bufA) ? bufB : bufA;
    }
    out_kernel<<<NN / 8, 256>>>(x, W_out, b_out, out);
}